// round 10
// baseline (speedup 1.0000x reference)
#include <cuda_runtime.h>
#include <cstdint>

#define TPB 128
typedef unsigned long long u64;

__device__ __forceinline__ u64 ffma2(u64 a, u64 b, u64 c) {
    u64 d;
    asm("fma.rn.f32x2 %0, %1, %2, %3;" : "=l"(d) : "l"(a), "l"(b), "l"(c));
    return d;
}
__device__ __forceinline__ u64 addf2(u64 a, u64 b) {
    u64 d;
    asm("add.rn.f32x2 %0, %1, %2;" : "=l"(d) : "l"(a), "l"(b));
    return d;
}
__device__ __forceinline__ u64 pack2(float lo, float hi) {
    u64 d;
    unsigned a = __float_as_uint(lo), b = __float_as_uint(hi);
    asm("mov.b64 %0, {%1,%2};" : "=l"(d) : "r"(a), "r"(b));
    return d;
}
__device__ __forceinline__ u64 dup2(float v) {
    u64 d;
    unsigned a = __float_as_uint(v);
    asm("mov.b64 %0, {%1,%1};" : "=l"(d) : "r"(a));
    return d;
}
__device__ __forceinline__ void unpack2(u64 d, float& lo, float& hi) {
    unsigned a, b;
    asm("mov.b64 {%0,%1}, %2;" : "=r"(a), "=r"(b) : "l"(d));
    lo = __uint_as_float(a);
    hi = __uint_as_float(b);
}
__device__ __forceinline__ float tanh_fast(float v) {
    float r;
    asm("tanh.approx.f32 %0, %1;" : "=f"(r) : "f"(v));
    return r;
}
template<int OFF>
__device__ __forceinline__ float lds32(unsigned a) {
    float v;
    asm volatile("ld.shared.f32 %0, [%1+%2];" : "=f"(v) : "r"(a), "n"(OFF));
    return v;
}
__device__ __forceinline__ void cp16(unsigned dst, const void* src) {
    asm volatile("cp.async.cg.shared.global [%0], [%1], 16;"
                 :: "r"(dst), "l"(src) : "memory");
}
__device__ __forceinline__ void cp_commit() {
    asm volatile("cp.async.commit_group;" ::: "memory");
}
__device__ __forceinline__ void cp_wait_all() {
    asm volatile("cp.async.wait_group 0;" ::: "memory");
}

// W1 chain for ONE row: 8 broadcast z loads, in-register dup, 32 packed FMAs
// into 4 feature-packed accumulators.
__device__ __forceinline__ void w1_chain(unsigned za,
                                         const u64 (&w1p)[8][4],
                                         const u64 (&b1p)[4],
                                         u64 (&a)[4])
{
    float f0 = lds32< 0>(za);
    float f1 = lds32< 4>(za);
    float f2 = lds32< 8>(za);
    float f3 = lds32<12>(za);
    float f4 = lds32<16>(za);
    float f5 = lds32<20>(za);
    float f6 = lds32<24>(za);
    float f7 = lds32<28>(za);

    u64 z0 = dup2(f0), z1 = dup2(f1), z2 = dup2(f2), z3 = dup2(f3);
    u64 z4 = dup2(f4), z5 = dup2(f5), z6 = dup2(f6), z7 = dup2(f7);

    a[0] = ffma2(z0, w1p[0][0], b1p[0]);
    a[1] = ffma2(z0, w1p[0][1], b1p[1]);
    a[2] = ffma2(z0, w1p[0][2], b1p[2]);
    a[3] = ffma2(z0, w1p[0][3], b1p[3]);
    a[0] = ffma2(z1, w1p[1][0], a[0]); a[1] = ffma2(z1, w1p[1][1], a[1]);
    a[2] = ffma2(z1, w1p[1][2], a[2]); a[3] = ffma2(z1, w1p[1][3], a[3]);
    a[0] = ffma2(z2, w1p[2][0], a[0]); a[1] = ffma2(z2, w1p[2][1], a[1]);
    a[2] = ffma2(z2, w1p[2][2], a[2]); a[3] = ffma2(z2, w1p[2][3], a[3]);
    a[0] = ffma2(z3, w1p[3][0], a[0]); a[1] = ffma2(z3, w1p[3][1], a[1]);
    a[2] = ffma2(z3, w1p[3][2], a[2]); a[3] = ffma2(z3, w1p[3][3], a[3]);
    a[0] = ffma2(z4, w1p[4][0], a[0]); a[1] = ffma2(z4, w1p[4][1], a[1]);
    a[2] = ffma2(z4, w1p[4][2], a[2]); a[3] = ffma2(z4, w1p[4][3], a[3]);
    a[0] = ffma2(z5, w1p[5][0], a[0]); a[1] = ffma2(z5, w1p[5][1], a[1]);
    a[2] = ffma2(z5, w1p[5][2], a[2]); a[3] = ffma2(z5, w1p[5][3], a[3]);
    a[0] = ffma2(z6, w1p[6][0], a[0]); a[1] = ffma2(z6, w1p[6][1], a[1]);
    a[2] = ffma2(z6, w1p[6][2], a[2]); a[3] = ffma2(z6, w1p[6][3], a[3]);
    a[0] = ffma2(z7, w1p[7][0], a[0]); a[1] = ffma2(z7, w1p[7][1], a[1]);
    a[2] = ffma2(z7, w1p[7][2], a[2]); a[3] = ffma2(z7, w1p[7][3], a[3]);
}

// tanh + W2 dot (two independent packed sub-chains) -> this fg's partial y
__device__ __forceinline__ float epi(const u64 (&a)[4],
                                     const u64 (&w2p)[4],
                                     u64 biaspack)
{
    float h0, h1, h2, h3, h4, h5, h6, h7;
    unpack2(a[0], h0, h1); unpack2(a[1], h2, h3);
    unpack2(a[2], h4, h5); unpack2(a[3], h6, h7);
    h0 = tanh_fast(h0); h1 = tanh_fast(h1);
    h2 = tanh_fast(h2); h3 = tanh_fast(h3);
    h4 = tanh_fast(h4); h5 = tanh_fast(h5);
    h6 = tanh_fast(h6); h7 = tanh_fast(h7);
    u64 p0 = ffma2(pack2(h0, h1), w2p[0], biaspack);
    u64 p1 = ffma2(pack2(h4, h5), w2p[2], pack2(0.0f, 0.0f));
    p0 = ffma2(pack2(h2, h3), w2p[1], p0);
    p1 = ffma2(pack2(h6, h7), w2p[3], p1);
    float lo, hi;
    unpack2(addf2(p0, p1), lo, hi);
    return lo + hi;
}

// reduce over fg (xor8 + xor16); every lane gets the full y
__device__ __forceinline__ float reduce_fg(float y) {
    y += __shfl_xor_sync(0xffffffffu, y, 8);
    y += __shfl_xor_sync(0xffffffffu, y, 16);
    return y;
}

// stage one 32x32 tile (+wrap cols) into SMEM buffer via cp.async;
// offsets recomputed here to avoid pinning registers across the main loop
__device__ __forceinline__ void stage_tile(unsigned sb, const char* src, int tid)
{
    const int m0 = tid * 2;
    cp16(sb + (unsigned)((m0 >> 3) * 160 + (m0 & 7) * 16),
         src + m0 * 16);
    cp16(sb + (unsigned)(((m0 + 1) >> 3) * 160 + ((m0 + 1) & 7) * 16),
         src + (m0 + 1) * 16);
    if (tid < 64)
        cp16(sb + (unsigned)((tid >> 1) * 160 + 128 + (tid & 1) * 16),
             src + (tid >> 1) * 128 + (tid & 1) * 16);
    cp_commit();
}

__global__ void __launch_bounds__(TPB, 4)
fans_kernel(const float* __restrict__ x,
            const float* __restrict__ W1,
            const float* __restrict__ b1,
            const float* __restrict__ W2,
            const float* __restrict__ b2,
            float* __restrict__ out,
            int ntiles)
{
    // RAW x tile: 32 rows x 40 cols fp32 (slots 32..39 mirror cols 0..7 so
    // every neuron's window cols n..n+7 is contiguous). Double-buffered.
    __shared__ __align__(16) float xs[2][32][40];   // 10 KB

    const int tid  = threadIdx.x;
    const int lane = tid & 31;
    const int warp = tid >> 5;
    const int nl   = lane & 7;
    const int fg   = lane >> 3;       // 0..3, feature group of 8
    const int n    = warp * 8 + nl;   // neuron 0..31

    // ---- register-resident weight slice (loaded once) ----
    // window position t reads col (n+t)%32; sorted (np.nonzero) order maps
    // that to k = (t + wrap) % 8, wrap = max(0, n+8-32): pre-rotate W1.
    const int wrapc = (n + 8 > 32) ? (n + 8 - 32) : 0;
    u64 w1p[8][4];
    #pragma unroll
    for (int t = 0; t < 8; t++) {
        int k = t + wrapc;
        if (k >= 8) k -= 8;
        const float* wp = W1 + n * 256 + k * 32 + fg * 8;
        ulonglong2 a = *(const ulonglong2*)wp;
        ulonglong2 b = *(const ulonglong2*)(wp + 4);
        w1p[t][0] = a.x; w1p[t][1] = a.y; w1p[t][2] = b.x; w1p[t][3] = b.y;
    }
    u64 b1p[4];
    {
        const float* bp = b1 + n * 32 + fg * 8;
        ulonglong2 a = *(const ulonglong2*)bp;
        ulonglong2 b = *(const ulonglong2*)(bp + 4);
        b1p[0] = a.x; b1p[1] = a.y; b1p[2] = b.x; b1p[3] = b.y;
    }
    u64 w2p[4];
    {
        const float* wp = W2 + n * 32 + fg * 8;
        ulonglong2 a = *(const ulonglong2*)wp;
        ulonglong2 b = *(const ulonglong2*)(wp + 4);
        w2p[0] = a.x; w2p[1] = a.y; w2p[2] = b.x; w2p[3] = b.y;
    }
    const u64 biaspack = pack2((fg == 0) ? b2[n] : 0.0f, 0.0f);

    unsigned sbase;
    asm("{ .reg .u64 t; cvta.to.shared.u64 t, %1; cvt.u32.u64 %0, t; }"
        : "=r"(sbase) : "l"(&xs[0][0][0]));
    const unsigned zb = sbase + (unsigned)(n * 4);   // window base = col n

    int tile = blockIdx.x;
    if (tile >= ntiles) return;
    const char* gxb = (const char*)x;

    stage_tile(sbase, gxb + (size_t)tile * 4096, tid);
    cp_wait_all();
    __syncthreads();

    int buf = 0;
    for (;;) {
        const int next = tile + gridDim.x;
        const bool have_next = next < ntiles;
        if (have_next)
            stage_tile(sbase + (unsigned)((buf ^ 1) * 5120),
                       gxb + (size_t)next * 4096, tid);

        // ---- 32 rows, single-row software pipeline with role swap:
        //      chain(row r) overlaps epi(row r-1); no A<-B copies ----
        float* op = out + (size_t)tile * 1024 + n;   // fg==0 lanes store
        unsigned za = zb + (unsigned)(buf * 5120);

        u64 A[4], Bx[4];
        w1_chain(za, w1p, b1p, A);
        za += 160;

        #pragma unroll 1
        for (int r = 1; r < 31; r += 2) {
            w1_chain(za, w1p, b1p, Bx);
            za += 160;
            float ya = reduce_fg(epi(A, w2p, biaspack));
            if (fg == 0) op[0] = ya;

            w1_chain(za, w1p, b1p, A);
            za += 160;
            float yb = reduce_fg(epi(Bx, w2p, biaspack));
            if (fg == 0) op[32] = yb;
            op += 64;
        }

        // rows 30, 31 drain
        w1_chain(za, w1p, b1p, Bx);
        {
            float ya = reduce_fg(epi(A, w2p, biaspack));
            if (fg == 0) op[0] = ya;
            float yb = reduce_fg(epi(Bx, w2p, biaspack));
            if (fg == 0) op[32] = yb;
        }

        if (!have_next) break;
        cp_wait_all();
        __syncthreads();
        buf ^= 1;
        tile = next;
    }
}

extern "C" void kernel_launch(void* const* d_in, const int* in_sizes, int n_in,
                              void* d_out, int out_size) {
    const float* x  = (const float*)d_in[0];
    const float* W1 = (const float*)d_in[1];
    const float* b1 = (const float*)d_in[2];
    const float* W2 = (const float*)d_in[3];
    const float* b2 = (const float*)d_in[4];
    // d_in[5] (idx) unused: circular window + np.nonzero sort order are
    // reproduced analytically (W1 k-rotation at register-load time).
    float* out = (float*)d_out;

    const int B = in_sizes[0] / 32;
    const int ntiles = B / 32;
    int grid = 148 * 4;                  // persistent, 4 blocks/SM
    if (grid > ntiles) grid = ntiles;
    fans_kernel<<<grid, TPB>>>(x, W1, b1, W2, b2, out, ntiles);
}